// round 3
// baseline (speedup 1.0000x reference)
#include <cuda_runtime.h>
#include <math.h>

#define BB 2
#define SS 2048
#define EE 1024
#define HH 16
#define HD 64
#define MTOT (BB*SS)
#define SCALE 0.125f   // 1/sqrt(64)

// Scratch (allocation-free rule): device globals
__device__ float g_q[MTOT * EE];
__device__ float g_k[MTOT * EE];
__device__ float g_v[MTOT * EE];
__device__ float g_att[MTOT * EE];

// ---------------------------------------------------------------------------
// tf32 helpers
// ---------------------------------------------------------------------------
__device__ __forceinline__ unsigned f2tf(float f) {
    unsigned r;
    asm("cvt.rna.tf32.f32 %0, %1;" : "=r"(r) : "f"(f));
    return r;
}

__device__ __forceinline__ void mma_tf32(float c[4], const unsigned a[4], const unsigned b[2]) {
    asm volatile(
        "mma.sync.aligned.m16n8k8.row.col.f32.tf32.tf32.f32 "
        "{%0,%1,%2,%3}, {%4,%5,%6,%7}, {%8,%9}, {%0,%1,%2,%3};"
        : "+f"(c[0]), "+f"(c[1]), "+f"(c[2]), "+f"(c[3])
        : "r"(a[0]), "r"(a[1]), "r"(a[2]), "r"(a[3]), "r"(b[0]), "r"(b[1]));
}

// Reorder x so that slot tt receives original component (tt ^ ks)
__device__ __forceinline__ void perm4(unsigned x[4], int ks) {
    if (ks & 1) { unsigned tp = x[0]; x[0] = x[1]; x[1] = tp; tp = x[2]; x[2] = x[3]; x[3] = tp; }
    if (ks & 2) { unsigned tp = x[0]; x[0] = x[2]; x[2] = tp; tp = x[1]; x[1] = x[3]; x[3] = tp; }
}

// ---------------------------------------------------------------------------
// GEMM: C[M,N] = A[M,K] @ W[N,K]^T + bias   (M=4096, N=K=1024)
// CTA 128x128x32, 256 threads (8 warps: 2 in M x 4 in N), warp tile 64x32.
// Fragment-major smem: A frag = LDS.128, B frag = LDS.64, double-buffered.
//   A word addr = (mt*4+ks)*128 + g*16 + ((t^ks)&3)*4 + reg   (reg=khalf*2+rbit)
//   B word addr = (nt*4+ks)*64  + g*8  + ((t^ks)&3)*2 + khalf
// ---------------------------------------------------------------------------
struct QKVArgs {
    const float* A[3];
    const float* W[3];
    const float* bias[3];
    float*       C[3];
};

__device__ __forceinline__ void gemm_body(
    const float* __restrict__ A, const float* __restrict__ W,
    const float* __restrict__ bias, float* __restrict__ C)
{
    extern __shared__ unsigned sm[];   // 2 buffers x (A:4096 + B:4096) words

    const int tid  = threadIdx.x;
    const int warp = tid >> 5, lane = tid & 31;
    const int g = lane >> 2, t = lane & 3;
    const int wm = warp & 1, wn = warp >> 1;
    const int bm = blockIdx.y * 128, bn = blockIdx.x * 128;

    // ---- staging constants (loop-invariant)
    const int kq   = tid & 7;           // k-quad: fixed per thread
    const int ks_w = kq >> 1, kh_w = kq & 1;
    const int m0   = tid >> 3;          // rows m0 + i*32
    const int mt0  = m0 >> 4, rr = m0 & 15;
    const int gA   = rr & 7,  rb = rr >> 3;
    const int wbA  = (mt0 * 4 + ks_w) * 128 + gA * 16 + kh_w * 2 + rb;   // + i*1024 + tt*4
    const int wbB  = ((m0 >> 3) * 4 + ks_w) * 64 + (m0 & 7) * 8 + kh_w;  // + i*1024 + tt*2

    const float* Arow = A + (size_t)(bm + m0) * EE + kq * 4;
    const float* Wrow = W + (size_t)(bn + m0) * EE + kq * 4;

    float4 ra[4], rbv[4];
    float acc[4][4][4] = {};

    // preload tile 0
    #pragma unroll
    for (int i = 0; i < 4; i++) {
        ra[i]  = *(const float4*)(Arow + (size_t)i * 32 * EE);
        rbv[i] = *(const float4*)(Wrow + (size_t)i * 32 * EE);
    }
    // commit tile 0 -> buf0
    {
        unsigned* buf = sm;
        #pragma unroll
        for (int i = 0; i < 4; i++) {
            unsigned xa[4] = { f2tf(ra[i].x), f2tf(ra[i].y), f2tf(ra[i].z), f2tf(ra[i].w) };
            perm4(xa, ks_w);
            unsigned* p = buf + wbA + i * 1024;
            p[0] = xa[0]; p[4] = xa[1]; p[8] = xa[2]; p[12] = xa[3];
            unsigned xb[4] = { f2tf(rbv[i].x), f2tf(rbv[i].y), f2tf(rbv[i].z), f2tf(rbv[i].w) };
            perm4(xb, ks_w);
            unsigned* q = buf + 4096 + wbB + i * 1024;
            q[0] = xb[0]; q[2] = xb[1]; q[4] = xb[2]; q[6] = xb[3];
        }
    }
    __syncthreads();
    // preload tile 1
    #pragma unroll
    for (int i = 0; i < 4; i++) {
        ra[i]  = *(const float4*)(Arow + (size_t)i * 32 * EE + 32);
        rbv[i] = *(const float4*)(Wrow + (size_t)i * 32 * EE + 32);
    }

    const int NK = EE / 32;   // 32
    for (int kt = 0; kt < NK; kt++) {
        const unsigned* As = sm + (kt & 1) * 8192;
        const unsigned* Bs = As + 4096;

        // ---- compute 4 k-steps
        #pragma unroll
        for (int ksc = 0; ksc < 4; ksc++) {
            const int pa = g * 16 + ((t ^ ksc) & 3) * 4;
            const int pb = g * 8  + ((t ^ ksc) & 3) * 2;
            unsigned af[4][4], bf[4][2];
            #pragma unroll
            for (int mi = 0; mi < 4; mi++) {
                uint4 v = *(const uint4*)(As + ((wm * 4 + mi) * 4 + ksc) * 128 + pa);
                af[mi][0] = v.x; af[mi][1] = v.y; af[mi][2] = v.z; af[mi][3] = v.w;
            }
            #pragma unroll
            for (int ni = 0; ni < 4; ni++) {
                uint2 v = *(const uint2*)(Bs + ((wn * 4 + ni) * 4 + ksc) * 64 + pb);
                bf[ni][0] = v.x; bf[ni][1] = v.y;
            }
            #pragma unroll
            for (int mi = 0; mi < 4; mi++)
                #pragma unroll
                for (int ni = 0; ni < 4; ni++)
                    mma_tf32(acc[mi][ni], af[mi], bf[ni]);
        }

        if (kt + 1 < NK) {
            // commit tile kt+1 into the other buffer
            unsigned* buf = sm + ((kt + 1) & 1) * 8192;
            #pragma unroll
            for (int i = 0; i < 4; i++) {
                unsigned xa[4] = { f2tf(ra[i].x), f2tf(ra[i].y), f2tf(ra[i].z), f2tf(ra[i].w) };
                perm4(xa, ks_w);
                unsigned* p = buf + wbA + i * 1024;
                p[0] = xa[0]; p[4] = xa[1]; p[8] = xa[2]; p[12] = xa[3];
                unsigned xb[4] = { f2tf(rbv[i].x), f2tf(rbv[i].y), f2tf(rbv[i].z), f2tf(rbv[i].w) };
                perm4(xb, ks_w);
                unsigned* q = buf + 4096 + wbB + i * 1024;
                q[0] = xb[0]; q[2] = xb[1]; q[4] = xb[2]; q[6] = xb[3];
            }
            __syncthreads();
            if (kt + 2 < NK) {
                #pragma unroll
                for (int i = 0; i < 4; i++) {
                    ra[i]  = *(const float4*)(Arow + (size_t)i * 32 * EE + (kt + 2) * 32);
                    rbv[i] = *(const float4*)(Wrow + (size_t)i * 32 * EE + (kt + 2) * 32);
                }
            }
        }
    }

    // ---- epilogue
    #pragma unroll
    for (int mi = 0; mi < 4; mi++) {
        #pragma unroll
        for (int r2 = 0; r2 < 2; r2++) {
            int m = bm + wm * 64 + mi * 16 + g + r2 * 8;
            #pragma unroll
            for (int ni = 0; ni < 4; ni++) {
                int n = bn + wn * 32 + ni * 8 + 2 * t;
                float2 bv = *(const float2*)(bias + n);
                float2 o;
                o.x = acc[mi][ni][r2 * 2 + 0] + bv.x;
                o.y = acc[mi][ni][r2 * 2 + 1] + bv.y;
                *(float2*)(C + (size_t)m * EE + n) = o;
            }
        }
    }
}

__global__ __launch_bounds__(256) void qkv_gemm(QKVArgs args) {
    int z = blockIdx.z;
    gemm_body(args.A[z], args.W[z], args.bias[z], args.C[z]);
}

__global__ __launch_bounds__(256) void out_gemm(const float* __restrict__ A,
                                                const float* __restrict__ W,
                                                const float* __restrict__ bias,
                                                float* __restrict__ C) {
    gemm_body(A, W, bias, C);
}

// ---------------------------------------------------------------------------
// Flash attention, tf32 mma, fragment-major smem.
// Block = (b, h, 64 q-rows), 128 threads (4 warps, 16 rows each), 3 CTAs/SM.
// Kf (S-phase B, n=kv,k=d):  addr = (nt*8+ks)*64 + g*8 + ((t^ks)&3)*2 + khalf
// Vf (PV B, n=d,k=kv):       addr = (nt*8+ks)*64 + ((g*8+t*2+khalf) ^ swv(nt))
//                            swv(nt) = ((nt&3)<<3) | (((nt>>2)&1)<<1)
// Pf (PV A, per warp):       addr = (warp*8+ks)*128 + (g*4 + (t^((g>>1)&3)))*4 + reg
// Q staged once into Kf in A-frag layout, pulled to registers.
// ---------------------------------------------------------------------------
__global__ __launch_bounds__(128, 3) void attn_tc() {
    extern __shared__ unsigned sm[];
    unsigned* Kf = sm;              // 4096 words
    unsigned* Vf = sm + 4096;       // 4096 words
    unsigned* Pf = sm + 8192;       // 4096 words

    const int tid  = threadIdx.x;
    const int warp = tid >> 5, lane = tid & 31;
    const int g = lane >> 2, t = lane & 3;
    const int b = blockIdx.x >> 4, h = blockIdx.x & 15;
    const int q0 = blockIdx.y * 64;
    const size_t base = (size_t)b * SS * EE + (size_t)h * HD;

    // staging thread constants
    const int r0  = tid >> 4;        // 0..7
    const int c4  = tid & 15;        // 0..15
    const int ksS = c4 >> 1, khS = c4 & 1;          // k-slab from columns (K, Q)
    const int wbK = ksS * 64 + r0 * 8 + khS;        // + i*512 + tt*2
    const int ntV = c4 >> 1;
    const int swV = ((ntV & 3) << 3) | (((ntV >> 2) & 1) << 1);
    const int tV  = r0 & 3, khV = (r0 >> 2) & 1;
    int offV[4];
    #pragma unroll
    for (int j = 0; j < 4; j++)
        offV[j] = ntV * 512 + (((((c4 & 1) * 4 + j) * 8) + tV * 2 + khV) ^ swV);

    // ---- stage Q (scaled, tf32) into Kf in A-frag layout
    {
        const float* qrow = g_q + base + (size_t)(q0 + r0) * EE + c4 * 4;
        #pragma unroll
        for (int i = 0; i < 8; i++) {
            float4 v = *(const float4*)(qrow + (size_t)i * 8 * EE);
            unsigned x[4] = { f2tf(v.x * SCALE), f2tf(v.y * SCALE),
                              f2tf(v.z * SCALE), f2tf(v.w * SCALE) };
            perm4(x, ksS);
            unsigned* p = Kf + ((i >> 1) * 8 + ksS) * 128 + r0 * 16 + khS * 2 + (i & 1);
            p[0] = x[0]; p[4] = x[1]; p[8] = x[2]; p[12] = x[3];
        }
    }
    __syncthreads();
    unsigned qf[8][4];
    #pragma unroll
    for (int ks = 0; ks < 8; ks++) {
        uint4 v = *(const uint4*)(Kf + (warp * 8 + ks) * 128 + g * 16 + ((t ^ ks) & 3) * 4);
        qf[ks][0] = v.x; qf[ks][1] = v.y; qf[ks][2] = v.z; qf[ks][3] = v.w;
    }
    __syncthreads();

    float o[8][4] = {};
    float mrow0 = -1e30f, mrow1 = -1e30f, lrow0 = 0.f, lrow1 = 0.f;

    const float* krow = g_k + base + (size_t)r0 * EE + c4 * 4;
    const float* vrow = g_v + base + (size_t)r0 * EE + c4 * 4;

    for (int kt = 0; kt < SS / 64; kt++) {
        // ---- stage K, V (tf32, fragment-major)
        const size_t toff = (size_t)kt * 64 * EE;
        #pragma unroll
        for (int i = 0; i < 8; i++) {
            float4 kv = *(const float4*)(krow + toff + (size_t)i * 8 * EE);
            float4 vv = *(const float4*)(vrow + toff + (size_t)i * 8 * EE);
            unsigned xk[4] = { f2tf(kv.x), f2tf(kv.y), f2tf(kv.z), f2tf(kv.w) };
            perm4(xk, ksS);
            unsigned* p = Kf + i * 512 + wbK;
            p[0] = xk[0]; p[2] = xk[1]; p[4] = xk[2]; p[6] = xk[3];
            Vf[offV[0] + i * 64] = f2tf(vv.x);
            Vf[offV[1] + i * 64] = f2tf(vv.y);
            Vf[offV[2] + i * 64] = f2tf(vv.z);
            Vf[offV[3] + i * 64] = f2tf(vv.w);
        }
        __syncthreads();

        // ---- S = Q @ K^T
        float s[8][4] = {};
        #pragma unroll
        for (int ks = 0; ks < 8; ks++) {
            const int pb = g * 8 + ((t ^ ks) & 3) * 2;
            #pragma unroll
            for (int ni = 0; ni < 8; ni++) {
                uint2 bv = *(const uint2*)(Kf + (ni * 8 + ks) * 64 + pb);
                unsigned bb[2] = { bv.x, bv.y };
                mma_tf32(s[ni], qf[ks], bb);
            }
        }

        // ---- online softmax (rows g and g+8; reduce over lanes t)
        float mx0 = -1e30f, mx1 = -1e30f;
        #pragma unroll
        for (int ni = 0; ni < 8; ni++) {
            mx0 = fmaxf(mx0, fmaxf(s[ni][0], s[ni][1]));
            mx1 = fmaxf(mx1, fmaxf(s[ni][2], s[ni][3]));
        }
        mx0 = fmaxf(mx0, __shfl_xor_sync(0xffffffffu, mx0, 1));
        mx0 = fmaxf(mx0, __shfl_xor_sync(0xffffffffu, mx0, 2));
        mx1 = fmaxf(mx1, __shfl_xor_sync(0xffffffffu, mx1, 1));
        mx1 = fmaxf(mx1, __shfl_xor_sync(0xffffffffu, mx1, 2));

        float mn0 = fmaxf(mrow0, mx0), mn1 = fmaxf(mrow1, mx1);
        float c0 = __expf(mrow0 - mn0), c1 = __expf(mrow1 - mn1);
        float sum0 = 0.f, sum1 = 0.f;
        #pragma unroll
        for (int ni = 0; ni < 8; ni++) {
            s[ni][0] = __expf(s[ni][0] - mn0);
            s[ni][1] = __expf(s[ni][1] - mn0);
            s[ni][2] = __expf(s[ni][2] - mn1);
            s[ni][3] = __expf(s[ni][3] - mn1);
            sum0 += s[ni][0] + s[ni][1];
            sum1 += s[ni][2] + s[ni][3];
        }
        sum0 += __shfl_xor_sync(0xffffffffu, sum0, 1);
        sum0 += __shfl_xor_sync(0xffffffffu, sum0, 2);
        sum1 += __shfl_xor_sync(0xffffffffu, sum1, 1);
        sum1 += __shfl_xor_sync(0xffffffffu, sum1, 2);
        lrow0 = lrow0 * c0 + sum0;  mrow0 = mn0;
        lrow1 = lrow1 * c1 + sum1;  mrow1 = mn1;
        #pragma unroll
        for (int ni = 0; ni < 8; ni++) {
            o[ni][0] *= c0; o[ni][1] *= c0;
            o[ni][2] *= c1; o[ni][3] *= c1;
        }

        // ---- write P (tf32) into warp-local Pf in A-frag layout
        {
            const int xg = (g >> 1) & 3;
            #pragma unroll
            for (int ni = 0; ni < 8; ni++) {
                unsigned x0 = f2tf(s[ni][0]), x1 = f2tf(s[ni][1]);
                unsigned x2 = f2tf(s[ni][2]), x3 = f2tf(s[ni][3]);
                unsigned bp = (warp * 8 + ni) * 128 + (t >> 1) * 2;
                *(uint2*)(Pf + bp + (g * 4 + (((2 * t)     & 3) ^ xg)) * 4) = make_uint2(x0, x2);
                *(uint2*)(Pf + bp + (g * 4 + (((2 * t + 1) & 3) ^ xg)) * 4) = make_uint2(x1, x3);
            }
        }
        __syncwarp();

        // ---- O += P @ V
        #pragma unroll
        for (int ks = 0; ks < 8; ks++) {
            uint4 av = *(const uint4*)(Pf + (warp * 8 + ks) * 128 +
                                       (g * 4 + (t ^ ((g >> 1) & 3))) * 4);
            unsigned af[4] = { av.x, av.y, av.z, av.w };
            #pragma unroll
            for (int ni = 0; ni < 8; ni++) {
                const int swn = ((ni & 3) << 3) | (((ni >> 2) & 1) << 1);
                uint2 bv = *(const uint2*)(Vf + (ni * 8 + ks) * 64 + ((g * 8 + t * 2) ^ swn));
                unsigned bb[2] = { bv.x, bv.y };
                mma_tf32(o[ni], af, bb);
            }
        }
        __syncthreads();
    }

    // ---- normalize, store
    float inv0 = 1.f / lrow0, inv1 = 1.f / lrow1;
    int r0q = q0 + warp * 16 + g;
    #pragma unroll
    for (int ni = 0; ni < 8; ni++) {
        int d = h * HD + ni * 8 + 2 * t;
        float2 w0 = make_float2(o[ni][0] * inv0, o[ni][1] * inv0);
        float2 w1 = make_float2(o[ni][2] * inv1, o[ni][3] * inv1);
        *(float2*)(g_att + (size_t)(b * SS + r0q)     * EE + d) = w0;
        *(float2*)(g_att + (size_t)(b * SS + r0q + 8) * EE + d) = w1;
    }
}

// ---------------------------------------------------------------------------
// Launch
// ---------------------------------------------------------------------------
extern "C" void kernel_launch(void* const* d_in, const int* in_sizes, int n_in,
                              void* d_out, int out_size)
{
    const float* query = (const float*)d_in[0];
    const float* key_  = (const float*)d_in[1];
    const float* value = (const float*)d_in[2];
    const float* Wq = (const float*)d_in[3];
    const float* bq = (const float*)d_in[4];
    const float* Wk = (const float*)d_in[5];
    const float* bk = (const float*)d_in[6];
    const float* Wv = (const float*)d_in[7];
    const float* bv = (const float*)d_in[8];
    const float* Wo = (const float*)d_in[9];
    const float* bo = (const float*)d_in[10];
    float* out = (float*)d_out;

    float *q, *k, *v, *att;
    cudaGetSymbolAddress((void**)&q,   g_q);
    cudaGetSymbolAddress((void**)&k,   g_k);
    cudaGetSymbolAddress((void**)&v,   g_v);
    cudaGetSymbolAddress((void**)&att, g_att);

    static bool attr_done = false;
    if (!attr_done) {
        cudaFuncSetAttribute(qkv_gemm, cudaFuncAttributeMaxDynamicSharedMemorySize, 65536);
        cudaFuncSetAttribute(out_gemm, cudaFuncAttributeMaxDynamicSharedMemorySize, 65536);
        cudaFuncSetAttribute(attn_tc,  cudaFuncAttributeMaxDynamicSharedMemorySize, 49152);
        attr_done = true;
    }

    QKVArgs args;
    args.A[0] = query; args.A[1] = key_; args.A[2] = value;
    args.W[0] = Wq;    args.W[1] = Wk;   args.W[2] = Wv;
    args.bias[0] = bq; args.bias[1] = bk; args.bias[2] = bv;
    args.C[0] = q;     args.C[1] = k;    args.C[2] = v;

    dim3 gqkv(EE / 128, MTOT / 128, 3);
    qkv_gemm<<<gqkv, 256, 65536>>>(args);

    attn_tc<<<dim3(BB * HH, SS / 64), 128, 49152>>>();

    dim3 go(EE / 128, MTOT / 128);
    out_gemm<<<go, 256, 65536>>>(att, Wo, bo, out);
}